// round 10
// baseline (speedup 1.0000x reference)
#include <cuda_runtime.h>
#include <cuda_fp16.h>
#include <math.h>
#include <stdint.h>

// Problem constants (fixed by the dataset)
#define NNODES 200000
#define HSZ    256
#define XSZ    256
#define KK     512          // packed K = XSZ + HSZ
#define NOUT   1024         // packed cols, interleaved gate quads (i,o,u,f)

// ---------------- device scratch (static allocation) ------------------------
__device__ float g_hsum[NNODES * HSZ];                 // 200 MB
__device__ float g_csum[NNODES * HSZ];                 // 200 MB
__device__ __half g_Af[(size_t)NNODES * KK];           // 204.8 MB  A = [x|hsum] fp16
__device__ __half g_Bf[NOUT * KK];                     // 1 MB  [n][k] K-major
__device__ float g_bias[NOUT];

// ---------------- PTX helpers (baseline compute_103 only) -------------------
__device__ __forceinline__ uint32_t s2u(const void* p) {
    uint32_t a;
    asm("{ .reg .u64 t; cvta.to.shared.u64 t, %1; cvt.u32.u64 %0, t; }"
        : "=r"(a) : "l"(p));
    return a;
}
#define CPA16(dst, src) \
    asm volatile("cp.async.cg.shared.global [%0], [%1], 16;" :: "r"(dst), "l"(src) : "memory")
#define CPA_COMMIT() asm volatile("cp.async.commit_group;" ::: "memory")

__device__ __forceinline__ void ldsm4(uint32_t* r, uint32_t addr) {
    asm volatile("ldmatrix.sync.aligned.m8n8.x4.shared.b16 {%0,%1,%2,%3}, [%4];"
                 : "=r"(r[0]), "=r"(r[1]), "=r"(r[2]), "=r"(r[3]) : "r"(addr));
}
__device__ __forceinline__ void mma16816(float* d, const uint32_t* a, const uint32_t* b) {
    asm volatile("mma.sync.aligned.m16n8k16.row.col.f32.f16.f16.f32 "
                 "{%0,%1,%2,%3}, {%4,%5,%6,%7}, {%8,%9}, {%0,%1,%2,%3};"
                 : "+f"(d[0]), "+f"(d[1]), "+f"(d[2]), "+f"(d[3])
                 : "r"(a[0]), "r"(a[1]), "r"(a[2]), "r"(a[3]), "r"(b[0]), "r"(b[1]));
}
// vectorized f32 reduction (PTX ISA 8.1+, sm_90+, not arch-'a' gated)
__device__ __forceinline__ void red_add_v4(float* p, float4 v) {
    asm volatile("red.add.v4.f32 [%0], {%1, %2, %3, %4};"
                 :: "l"(p), "f"(v.x), "f"(v.y), "f"(v.z), "f"(v.w) : "memory");
}

// fast sigmoid/tanh via ex2/rcp approx (rel err ~1e-6)
__device__ __forceinline__ float fexp2_(float x) {
    float y; asm("ex2.approx.ftz.f32 %0, %1;" : "=f"(y) : "f"(x)); return y;
}
__device__ __forceinline__ float frcp_(float x) {
    float y; asm("rcp.approx.ftz.f32 %0, %1;" : "=f"(y) : "f"(x)); return y;
}
__device__ __forceinline__ float sig_(float x) {
    return frcp_(1.0f + fexp2_(-1.4426950408889634f * x));
}
__device__ __forceinline__ float tanh_(float x) {
    return 2.0f * frcp_(1.0f + fexp2_(-2.8853900817779268f * x)) - 1.0f;
}

// ---------------------------------------------------------------------------
// Kernel 0: zero accumulators
// ---------------------------------------------------------------------------
__global__ void zero_kernel() {
    long long idx = (long long)blockIdx.x * blockDim.x + threadIdx.x;
    long long total4 = (long long)NNODES * HSZ / 4;
    float4 z = make_float4(0.f, 0.f, 0.f, 0.f);
    for (long long i = idx; i < total4; i += (long long)gridDim.x * blockDim.x) {
        ((float4*)g_hsum)[i] = z;
        ((float4*)g_csum)[i] = z;
    }
}

// ---------------------------------------------------------------------------
// Kernel 1: pack weights -> fp16, layout [n][k] K-major, n = 4q+t
// ---------------------------------------------------------------------------
__global__ void pack_kernel(const float* __restrict__ Wiou,
                            const float* __restrict__ Uiou,
                            const float* __restrict__ biou,
                            const float* __restrict__ Ufw,
                            const float* __restrict__ Ufb) {
    int idx = blockIdx.x * blockDim.x + threadIdx.x;
    if (idx < NOUT * KK) {
        int n = idx >> 9;
        int k = idx & (KK - 1);
        int q = n >> 2;
        int t = n & 3;
        float v;
        if (k < 256) {
            v = (t < 3) ? Wiou[(t * 256 + q) * XSZ + k] : 0.0f;
        } else {
            int kk = k - 256;
            v = (t < 3) ? Uiou[(t * 256 + q) * HSZ + kk] : Ufw[q * HSZ + kk];
        }
        g_Bf[idx] = __float2half_rn(v);
    }
    if (idx < NOUT) {
        int q = idx >> 2;
        int t = idx & 3;
        g_bias[idx] = (t < 3) ? biou[t * 256 + q] : Ufb[q];
    }
}

// ---------------------------------------------------------------------------
// Kernel 2: edge scatter-add with vectorized f32 reductions
// ---------------------------------------------------------------------------
__global__ void scatter_kernel(const float* __restrict__ h,
                               const float* __restrict__ c,
                               const int* __restrict__ src,
                               const int* __restrict__ dst,
                               int E) {
    int e = blockIdx.x * 4 + (threadIdx.x >> 6);
    if (e >= E) return;
    int lane = threadIdx.x & 63;
    int s = src[e];
    int d = dst[e];
    int off = lane * 4;
    float4 hv = *(const float4*)&h[(long long)s * HSZ + off];
    float4 cv = *(const float4*)&c[(long long)s * HSZ + off];
    red_add_v4(&g_hsum[(long long)d * HSZ + off], hv);
    red_add_v4(&g_csum[(long long)d * HSZ + off], cv);
}

// ---------------------------------------------------------------------------
// Kernel 3: convert A = [x | hsum] -> fp16 [m][512]
// ---------------------------------------------------------------------------
__global__ void convert_kernel(const float* __restrict__ x, int M) {
    long long i = (long long)blockIdx.x * blockDim.x + threadIdx.x;
    long long total = (long long)M * 128;          // one float4 each
    if (i >= total) return;
    int m = (int)(i >> 7);
    int k = ((int)i & 127) * 4;
    const float* sp = (k < 256) ? &x[(long long)m * 256 + k]
                                : &g_hsum[(long long)m * 256 + (k - 256)];
    float4 v = *(const float4*)sp;
    __half2 h01 = __floats2half2_rn(v.x, v.y);
    __half2 h23 = __floats2half2_rn(v.z, v.w);
    long long off = (long long)m * KK + k;
    *(__half2*)&g_Af[off + 0] = h01;
    *(__half2*)&g_Af[off + 2] = h23;
}

// ---------------------------------------------------------------------------
// Kernel 4: fp16 mma.sync GEMM (128m x 256n x K512) + coalesced fused epilogue
//   64x64 warp tiles (2x4 warps): 0.25 ldsm/MMA, -33% smem crossbar traffic
// ---------------------------------------------------------------------------
#define BK        32
#define ROWB      80                       // padded row bytes (40 halves)
#define A_SEC     (128 * ROWB)             // 10240 B
#define B_SEC     (256 * ROWB)             // 20480 B
#define STAGE_B   (A_SEC + B_SEC)          // 30720 B
#define NSTG      4
#define KITERS    (KK / BK)                // 16
#define SST       264                      // epilogue smem row stride (words)
#define DYN_SMEM  (128 * SST * 4)          // 135168 B (>= 4*STAGE_B=122880)

__global__ void __launch_bounds__(256, 1)
gemm_mma_kernel(float* __restrict__ hout, float* __restrict__ cout, int M) {
    extern __shared__ __align__(128) char sm[];
    __shared__ __align__(16) float s_bias[256];

    const int tid  = threadIdx.x;
    const int lane = tid & 31;
    const int wid  = tid >> 5;
    const int wm   = wid >> 2;            // 0..1  (64-row band)
    const int wn   = wid & 3;             // 0..3  (64-col band)
    const int m0   = blockIdx.y * 128;
    const int n0   = blockIdx.x * 256;
    const uint32_t smb = s2u(sm);

    s_bias[tid] = g_bias[n0 + tid];

    // ---- stage loader: 1536 x 16B cp.async ---------------------------------
    auto load_stage = [&](int s) {
        const uint32_t base = smb + (s & (NSTG - 1)) * STAGE_B;
        const int k0 = s * BK;
#pragma unroll
        for (int i = 0; i < 6; i++) {
            int l = tid + i * 256;
            const __half* src;
            uint32_t dst;
            if (l < 512) {                 // A: 128 rows x 4 chunks
                int row = l >> 2;
                int ch = l & 3;
                int gr = m0 + row; if (gr >= M) gr = M - 1;
                src = g_Af + (long long)gr * KK + k0 + ch * 8;
                dst = base + row * ROWB + ch * 16;
            } else {                       // B: 256 rows x 4 chunks
                int lb = l - 512;
                int row = lb >> 2;
                int ch = lb & 3;
                src = g_Bf + (long long)(n0 + row) * KK + k0 + ch * 8;
                dst = base + A_SEC + row * ROWB + ch * 16;
            }
            CPA16(dst, src);
        }
        CPA_COMMIT();
    };

    load_stage(0);
    load_stage(1);
    load_stage(2);

    float acc[4][8][4];
#pragma unroll
    for (int i = 0; i < 4; i++)
#pragma unroll
        for (int j = 0; j < 8; j++)
#pragma unroll
            for (int p = 0; p < 4; p++) acc[i][j][p] = 0.0f;

    const uint32_t aRow = (wm * 64 + (lane & 15)) * ROWB + (lane >> 4) * 16;
    const uint32_t bRow = (wn * 64 + (lane & 7) + ((lane >> 4) & 1) * 8) * ROWB
                          + ((lane >> 3) & 1) * 16;

#pragma unroll 1
    for (int s = 0; s < KITERS; s++) {
        if (s <= KITERS - 3)      asm volatile("cp.async.wait_group 2;" ::: "memory");
        else if (s == KITERS - 2) asm volatile("cp.async.wait_group 1;" ::: "memory");
        else                      asm volatile("cp.async.wait_group 0;" ::: "memory");
        __syncthreads();
        if (s + 3 < KITERS) load_stage(s + 3);

        const uint32_t base = smb + (s & (NSTG - 1)) * STAGE_B;
#pragma unroll
        for (int t = 0; t < 2; t++) {
            const uint32_t kb = t * 32;
            uint32_t ah[4][4], bh[4][4];
#pragma unroll
            for (int i = 0; i < 4; i++)
                ldsm4(ah[i], base + aRow + i * 16 * ROWB + kb);
#pragma unroll
            for (int j = 0; j < 4; j++)
                ldsm4(bh[j], base + A_SEC + bRow + j * 16 * ROWB + kb);
#pragma unroll
            for (int i = 0; i < 4; i++) {
#pragma unroll
                for (int jt = 0; jt < 8; jt++) {
                    mma16816(acc[i][jt], ah[i], &bh[jt >> 1][(jt & 1) * 2]);
                }
            }
        }
    }

    // ---- epilogue phase 1: dump accumulators to smem ----------------------
    __syncthreads();            // all MMAs done; stage buffers reusable
    float* S = (float*)sm;      // [128][SST], logical col c -> phys c + 4 if c>=128
    {
        const int r0 = wm * 64 + (lane >> 2);
        const int c0 = wn * 64 + (lane & 3) * 2;
#pragma unroll
        for (int i = 0; i < 4; i++) {
#pragma unroll
            for (int jt = 0; jt < 8; jt++) {
                const int r = r0 + i * 16;
                const int c = c0 + jt * 8;
                const int phys = c + ((c >> 7) << 2);
                *(float2*)&S[r * SST + phys]       = make_float2(acc[i][jt][0], acc[i][jt][1]);
                *(float2*)&S[(r + 8) * SST + phys] = make_float2(acc[i][jt][2], acc[i][jt][3]);
            }
        }
    }
    __syncthreads();

    // ---- epilogue phase 2: coalesced TreeLSTM -----------------------------
    // thread -> (row = tid>>1, half = tid&1): 32 consecutive quads
    {
        const int row  = tid >> 1;
        const int half = tid & 1;
        const int mrow = m0 + row;
        if (mrow < M) {
            const long long mb = (long long)mrow * HSZ;
            const int qg0 = (n0 >> 2) + half * 32;        // first global q
            const float* Srow = &S[row * SST + half * 132];
            const float4* bq = &((const float4*)s_bias)[half * 32];
#pragma unroll
            for (int v = 0; v < 8; v++) {
                float4 csv = __ldcs((const float4*)&g_csum[mb + qg0 + v * 4]);
                float hv[4], cv[4];
#pragma unroll
                for (int u = 0; u < 4; u++) {
                    const int qq = v * 4 + u;
                    float4 z = *(const float4*)&Srow[qq * 4];
                    float4 b = bq[qq];
                    float zi = z.x + b.x, zo = z.y + b.y;
                    float zu = z.z + b.z, zf = z.w + b.w;
                    float cs = (&csv.x)[u];
                    float cn = sig_(zi) * tanh_(zu) + sig_(zf) * cs;
                    cv[u] = cn;
                    hv[u] = sig_(zo) * tanh_(cn);
                }
                __stcs((float4*)&hout[mb + qg0 + v * 4],
                       make_float4(hv[0], hv[1], hv[2], hv[3]));
                __stcs((float4*)&cout[mb + qg0 + v * 4],
                       make_float4(cv[0], cv[1], cv[2], cv[3]));
            }
        }
    }
}

// ---------------------------------------------------------------------------
// launch
// ---------------------------------------------------------------------------
extern "C" void kernel_launch(void* const* d_in, const int* in_sizes, int n_in,
                              void* d_out, int out_size) {
    const float* x    = (const float*)d_in[0];
    const float* h    = (const float*)d_in[1];
    const float* c    = (const float*)d_in[2];
    const int*   src  = (const int*)d_in[3];
    const int*   dst  = (const int*)d_in[4];
    const float* Wiou = (const float*)d_in[5];
    const float* Uiou = (const float*)d_in[6];
    const float* biou = (const float*)d_in[7];
    const float* Ufw  = (const float*)d_in[8];
    const float* Ufb  = (const float*)d_in[9];

    const int E = in_sizes[3];
    const int M = in_sizes[0] / XSZ;

    float* hout = (float*)d_out;
    float* cout = (float*)d_out + (long long)M * HSZ;

    cudaFuncSetAttribute(gemm_mma_kernel,
                         cudaFuncAttributeMaxDynamicSharedMemorySize, DYN_SMEM);

    zero_kernel<<<4096, 256>>>();
    pack_kernel<<<(NOUT * KK + 255) / 256, 256>>>(Wiou, Uiou, biou, Ufw, Ufb);
    scatter_kernel<<<(E + 3) / 4, 256>>>(h, c, src, dst, E);
    convert_kernel<<<(int)(((long long)M * 128 + 255) / 256), 256>>>(x, M);

    dim3 grid(NOUT / 256, (M + 127) / 128);
    gemm_mma_kernel<<<grid, 256, DYN_SMEM>>>(hout, cout, M);
}

// round 11
// speedup vs baseline: 1.2750x; 1.2750x over previous
#include <cuda_runtime.h>
#include <cuda_fp16.h>
#include <math.h>
#include <stdint.h>

// Problem constants (fixed by the dataset)
#define NNODES 200000
#define HSZ    256
#define XSZ    256
#define KK     512          // packed K = XSZ + HSZ
#define NOUT   1024         // packed cols, interleaved gate quads (i,o,u,f)

// ---------------- device scratch (static allocation) ------------------------
__device__ float g_hsum[NNODES * HSZ];                 // 200 MB
__device__ float g_csum[NNODES * HSZ];                 // 200 MB
__device__ __half g_Af[(size_t)NNODES * KK];           // 204.8 MB  A = [x|hsum] fp16
__device__ __half g_Bf[NOUT * KK];                     // 1 MB  [n][k] K-major
__device__ float g_bias[NOUT];

// ---------------- PTX helpers (baseline compute_103 only) -------------------
__device__ __forceinline__ uint32_t s2u(const void* p) {
    uint32_t a;
    asm("{ .reg .u64 t; cvta.to.shared.u64 t, %1; cvt.u32.u64 %0, t; }"
        : "=r"(a) : "l"(p));
    return a;
}
#define CPA16(dst, src) \
    asm volatile("cp.async.cg.shared.global [%0], [%1], 16;" :: "r"(dst), "l"(src) : "memory")
#define CPA_COMMIT() asm volatile("cp.async.commit_group;" ::: "memory")

__device__ __forceinline__ void ldsm4(uint32_t* r, uint32_t addr) {
    asm volatile("ldmatrix.sync.aligned.m8n8.x4.shared.b16 {%0,%1,%2,%3}, [%4];"
                 : "=r"(r[0]), "=r"(r[1]), "=r"(r[2]), "=r"(r[3]) : "r"(addr));
}
__device__ __forceinline__ void mma16816(float* d, const uint32_t* a, const uint32_t* b) {
    asm volatile("mma.sync.aligned.m16n8k16.row.col.f32.f16.f16.f32 "
                 "{%0,%1,%2,%3}, {%4,%5,%6,%7}, {%8,%9}, {%0,%1,%2,%3};"
                 : "+f"(d[0]), "+f"(d[1]), "+f"(d[2]), "+f"(d[3])
                 : "r"(a[0]), "r"(a[1]), "r"(a[2]), "r"(a[3]), "r"(b[0]), "r"(b[1]));
}
// vectorized f32 reduction (PTX ISA 8.1+, sm_90+, not arch-'a' gated)
__device__ __forceinline__ void red_add_v4(float* p, float4 v) {
    asm volatile("red.add.v4.f32 [%0], {%1, %2, %3, %4};"
                 :: "l"(p), "f"(v.x), "f"(v.y), "f"(v.z), "f"(v.w) : "memory");
}

// fast sigmoid/tanh via ex2/rcp approx (rel err ~1e-6)
__device__ __forceinline__ float fexp2_(float x) {
    float y; asm("ex2.approx.ftz.f32 %0, %1;" : "=f"(y) : "f"(x)); return y;
}
__device__ __forceinline__ float frcp_(float x) {
    float y; asm("rcp.approx.ftz.f32 %0, %1;" : "=f"(y) : "f"(x)); return y;
}
__device__ __forceinline__ float sig_(float x) {
    return frcp_(1.0f + fexp2_(-1.4426950408889634f * x));
}
__device__ __forceinline__ float tanh_(float x) {
    return 2.0f * frcp_(1.0f + fexp2_(-2.8853900817779268f * x)) - 1.0f;
}

// ---------------------------------------------------------------------------
// Kernel 0: zero accumulators
// ---------------------------------------------------------------------------
__global__ void zero_kernel() {
    long long idx = (long long)blockIdx.x * blockDim.x + threadIdx.x;
    long long total4 = (long long)NNODES * HSZ / 4;
    float4 z = make_float4(0.f, 0.f, 0.f, 0.f);
    for (long long i = idx; i < total4; i += (long long)gridDim.x * blockDim.x) {
        ((float4*)g_hsum)[i] = z;
        ((float4*)g_csum)[i] = z;
    }
}

// ---------------------------------------------------------------------------
// Kernel 1: pack weights -> fp16, layout [n][k] K-major, n = 4q+t
// ---------------------------------------------------------------------------
__global__ void pack_kernel(const float* __restrict__ Wiou,
                            const float* __restrict__ Uiou,
                            const float* __restrict__ biou,
                            const float* __restrict__ Ufw,
                            const float* __restrict__ Ufb) {
    int idx = blockIdx.x * blockDim.x + threadIdx.x;
    if (idx < NOUT * KK) {
        int n = idx >> 9;
        int k = idx & (KK - 1);
        int q = n >> 2;
        int t = n & 3;
        float v;
        if (k < 256) {
            v = (t < 3) ? Wiou[(t * 256 + q) * XSZ + k] : 0.0f;
        } else {
            int kk = k - 256;
            v = (t < 3) ? Uiou[(t * 256 + q) * HSZ + kk] : Ufw[q * HSZ + kk];
        }
        g_Bf[idx] = __float2half_rn(v);
    }
    if (idx < NOUT) {
        int q = idx >> 2;
        int t = idx & 3;
        g_bias[idx] = (t < 3) ? biou[t * 256 + q] : Ufb[q];
    }
}

// ---------------------------------------------------------------------------
// Kernel 2: edge scatter-add with vectorized f32 reductions
// ---------------------------------------------------------------------------
__global__ void scatter_kernel(const float* __restrict__ h,
                               const float* __restrict__ c,
                               const int* __restrict__ src,
                               const int* __restrict__ dst,
                               int E) {
    int e = blockIdx.x * 4 + (threadIdx.x >> 6);
    if (e >= E) return;
    int lane = threadIdx.x & 63;
    int s = src[e];
    int d = dst[e];
    int off = lane * 4;
    float4 hv = __ldcs((const float4*)&h[(long long)s * HSZ + off]);
    float4 cv = __ldcs((const float4*)&c[(long long)s * HSZ + off]);
    red_add_v4(&g_hsum[(long long)d * HSZ + off], hv);
    red_add_v4(&g_csum[(long long)d * HSZ + off], cv);
}

// ---------------------------------------------------------------------------
// Kernel 3: convert A = [x | hsum] -> fp16 [m][512]
// ---------------------------------------------------------------------------
__global__ void convert_kernel(const float* __restrict__ x, int M) {
    long long i = (long long)blockIdx.x * blockDim.x + threadIdx.x;
    long long total = (long long)M * 128;          // one float4 each
    if (i >= total) return;
    int m = (int)(i >> 7);
    int k = ((int)i & 127) * 4;
    const float* sp = (k < 256) ? &x[(long long)m * 256 + k]
                                : &g_hsum[(long long)m * 256 + (k - 256)];
    float4 v = *(const float4*)sp;
    __half2 h01 = __floats2half2_rn(v.x, v.y);
    __half2 h23 = __floats2half2_rn(v.z, v.w);
    long long off = (long long)m * KK + k;
    *(__half2*)&g_Af[off + 0] = h01;
    *(__half2*)&g_Af[off + 2] = h23;
}

// ---------------------------------------------------------------------------
// Kernel 4: fp16 mma.sync GEMM (128x128xK512, BK=64) + coalesced fused epilogue
//   3-stage cp.async pipeline, ONE __syncthreads per k-iteration (8 iters)
// ---------------------------------------------------------------------------
#define BK        64
#define ROWB      144                      // padded row bytes (72 halves)
#define SEC_B     (128 * ROWB)             // 18432 B per matrix section
#define STAGE_B   (2 * SEC_B)              // 36864 B
#define NSTG      3
#define KITERS    (KK / BK)                // 8
#define DYN_SMEM  (NSTG * STAGE_B)         // 110592 B
#define SST       136                      // epilogue smem row stride (words)

__global__ void __launch_bounds__(256, 2)
gemm_mma_kernel(float* __restrict__ hout, float* __restrict__ cout, int M) {
    extern __shared__ __align__(128) char sm[];
    __shared__ __align__(16) float s_bias[128];   // 16B-aligned: read as float4

    const int tid  = threadIdx.x;
    const int lane = tid & 31;
    const int wid  = tid >> 5;
    const int wm   = wid >> 2;            // 0..1  (64-row band)
    const int wn   = wid & 3;             // 0..3  (32-col band)
    const int m0   = blockIdx.y * 128;
    const int n0   = blockIdx.x * 128;
    const uint32_t smb = s2u(sm);

    if (tid < 128) s_bias[tid] = g_bias[n0 + tid];

    // ---- stage loader: 2048 x 16B cp.async ---------------------------------
    auto load_stage = [&](int s) {
        const uint32_t base = smb + (s % NSTG) * STAGE_B;
        const int k0 = s * BK;
#pragma unroll
        for (int i = 0; i < 8; i++) {
            int l = tid + i * 256;
            int sec = l >> 10;            // 0=A 1=B
            int w = l & 1023;
            int row = w >> 3;             // 0..127
            int ch = w & 7;               // 0..7 chunks of 8 halves
            const __half* src;
            if (sec == 0) {
                int gr = m0 + row; if (gr >= M) gr = M - 1;
                src = g_Af + (long long)gr * KK + k0 + ch * 8;
            } else {
                src = g_Bf + (long long)(n0 + row) * KK + k0 + ch * 8;
            }
            uint32_t dst = base + sec * SEC_B + row * ROWB + ch * 16;
            CPA16(dst, src);
        }
        CPA_COMMIT();
    };

    load_stage(0);
    load_stage(1);

    float acc[4][4][4];
#pragma unroll
    for (int i = 0; i < 4; i++)
#pragma unroll
        for (int j = 0; j < 4; j++)
#pragma unroll
            for (int p = 0; p < 4; p++) acc[i][j][p] = 0.0f;

    const uint32_t aRow = (wm * 64 + (lane & 15)) * ROWB + (lane >> 4) * 16;
    const uint32_t bRow = (wn * 32 + (lane & 7) + ((lane >> 4) & 1) * 8) * ROWB
                          + ((lane >> 3) & 1) * 16;

#pragma unroll 1
    for (int s = 0; s < KITERS; s++) {
        if (s < KITERS - 1) asm volatile("cp.async.wait_group 1;" ::: "memory");
        else                asm volatile("cp.async.wait_group 0;" ::: "memory");
        __syncthreads();
        // prefetch stage s+2 into buffer (s-1)%3 (consumed at iter s-1)
        if (s + 2 < KITERS) load_stage(s + 2);

        const uint32_t base = smb + (s % NSTG) * STAGE_B;
#pragma unroll
        for (int t = 0; t < 4; t++) {
            const uint32_t kb = t * 32;
            uint32_t ah[4][4], bh[2][4];
#pragma unroll
            for (int i = 0; i < 4; i++)
                ldsm4(ah[i], base + 0 * SEC_B + aRow + i * 16 * ROWB + kb);
#pragma unroll
            for (int j = 0; j < 2; j++)
                ldsm4(bh[j], base + 1 * SEC_B + bRow + j * 16 * ROWB + kb);
#pragma unroll
            for (int i = 0; i < 4; i++) {
#pragma unroll
                for (int jt = 0; jt < 4; jt++) {
                    mma16816(acc[i][jt], ah[i], &bh[jt >> 1][(jt & 1) * 2]);
                }
            }
        }
    }

    // ---- epilogue phase 1: dump accumulators to smem ----------------------
    __syncthreads();            // all MMAs done; stage buffers reusable
    float* S = (float*)sm;      // [128][SST]
    {
        const int r0 = wm * 64 + (lane >> 2);
        const int c0 = wn * 32 + (lane & 3) * 2;
#pragma unroll
        for (int i = 0; i < 4; i++) {
#pragma unroll
            for (int jt = 0; jt < 4; jt++) {
                const int r = r0 + i * 16;
                const int c = c0 + jt * 8;
                *(float2*)&S[r * SST + c]       = make_float2(acc[i][jt][0], acc[i][jt][1]);
                *(float2*)&S[(r + 8) * SST + c] = make_float2(acc[i][jt][2], acc[i][jt][3]);
            }
        }
    }
    __syncthreads();

    // ---- epilogue phase 2: coalesced TreeLSTM -----------------------------
    // thread -> (row = tid>>1, half = tid&1): 16 consecutive quads
    {
        const int row  = tid >> 1;
        const int half = tid & 1;
        const int mrow = m0 + row;
        if (mrow < M) {
            const long long mb = (long long)mrow * HSZ;
            const int qg0 = (n0 >> 2) + half * 16;        // first global q
            const float* Srow = &S[row * SST + half * 64];
            const float4* bq = &((const float4*)s_bias)[half * 16];
            float4 csv[4];
#pragma unroll
            for (int v = 0; v < 4; v++)
                csv[v] = __ldcs((const float4*)&g_csum[mb + qg0 + v * 4]);
#pragma unroll
            for (int v = 0; v < 4; v++) {
                float hv[4], cv[4];
#pragma unroll
                for (int u = 0; u < 4; u++) {
                    const int qq = v * 4 + u;
                    float4 z = *(const float4*)&Srow[qq * 4];
                    float4 b = bq[qq];
                    float zi = z.x + b.x, zo = z.y + b.y;
                    float zu = z.z + b.z, zf = z.w + b.w;
                    float cs = (&csv[v].x)[u];
                    float cn = sig_(zi) * tanh_(zu) + sig_(zf) * cs;
                    cv[u] = cn;
                    hv[u] = sig_(zo) * tanh_(cn);
                }
                __stcs((float4*)&hout[mb + qg0 + v * 4],
                       make_float4(hv[0], hv[1], hv[2], hv[3]));
                __stcs((float4*)&cout[mb + qg0 + v * 4],
                       make_float4(cv[0], cv[1], cv[2], cv[3]));
            }
        }
    }
}

// ---------------------------------------------------------------------------
// launch
// ---------------------------------------------------------------------------
extern "C" void kernel_launch(void* const* d_in, const int* in_sizes, int n_in,
                              void* d_out, int out_size) {
    const float* x    = (const float*)d_in[0];
    const float* h    = (const float*)d_in[1];
    const float* c    = (const float*)d_in[2];
    const int*   src  = (const int*)d_in[3];
    const int*   dst  = (const int*)d_in[4];
    const float* Wiou = (const float*)d_in[5];
    const float* Uiou = (const float*)d_in[6];
    const float* biou = (const float*)d_in[7];
    const float* Ufw  = (const float*)d_in[8];
    const float* Ufb  = (const float*)d_in[9];

    const int E = in_sizes[3];
    const int M = in_sizes[0] / XSZ;

    float* hout = (float*)d_out;
    float* cout = (float*)d_out + (long long)M * HSZ;

    cudaFuncSetAttribute(gemm_mma_kernel,
                         cudaFuncAttributeMaxDynamicSharedMemorySize, DYN_SMEM);

    zero_kernel<<<4096, 256>>>();
    pack_kernel<<<(NOUT * KK + 255) / 256, 256>>>(Wiou, Uiou, biou, Ufw, Ufb);
    scatter_kernel<<<(E + 3) / 4, 256>>>(h, c, src, dst, E);
    convert_kernel<<<(int)(((long long)M * 128 + 255) / 256), 256>>>(x, M);

    dim3 grid(NOUT / 128, (M + 127) / 128);
    gemm_mma_kernel<<<grid, 256, DYN_SMEM>>>(hout, cout, M);
}

// round 13
// speedup vs baseline: 1.4658x; 1.1496x over previous
#include <cuda_runtime.h>
#include <cuda_fp16.h>
#include <math.h>
#include <stdint.h>
#include <string.h>

// Problem constants (fixed by the dataset)
#define NNODES 200000
#define HSZ    256
#define XSZ    256
#define KK     512          // packed K = XSZ + HSZ
#define NOUT   1024         // packed cols, interleaved gate quads (i,o,u,f)

// ---------------- device scratch (static allocation) ------------------------
__device__ __half g_hsum[(size_t)NNODES * HSZ];        // 102.4 MB fp16 accumulator (= A's h-half)
__device__ __half g_csum[(size_t)NNODES * HSZ];        // 102.4 MB fp16 accumulator
__device__ __half g_Ax[(size_t)NNODES * XSZ];          // 102.4 MB x -> fp16
__device__ __half g_Bf[NOUT * KK];                     // 1 MB  [n][k] K-major
__device__ float g_bias[NOUT];

// ---------------- PTX helpers (baseline compute_103 only) -------------------
__device__ __forceinline__ uint32_t s2u(const void* p) {
    uint32_t a;
    asm("{ .reg .u64 t; cvta.to.shared.u64 t, %1; cvt.u32.u64 %0, t; }"
        : "=r"(a) : "l"(p));
    return a;
}
__device__ __forceinline__ uint32_t h2u(__half2 v) {
    uint32_t u;
    memcpy(&u, &v, 4);
    return u;
}
#define CPA16(dst, src) \
    asm volatile("cp.async.cg.shared.global [%0], [%1], 16;" :: "r"(dst), "l"(src) : "memory")
#define CPA_COMMIT() asm volatile("cp.async.commit_group;" ::: "memory")

__device__ __forceinline__ void ldsm4(uint32_t* r, uint32_t addr) {
    asm volatile("ldmatrix.sync.aligned.m8n8.x4.shared.b16 {%0,%1,%2,%3}, [%4];"
                 : "=r"(r[0]), "=r"(r[1]), "=r"(r[2]), "=r"(r[3]) : "r"(addr));
}
__device__ __forceinline__ void mma16816(float* d, const uint32_t* a, const uint32_t* b) {
    asm volatile("mma.sync.aligned.m16n8k16.row.col.f32.f16.f16.f32 "
                 "{%0,%1,%2,%3}, {%4,%5,%6,%7}, {%8,%9}, {%0,%1,%2,%3};"
                 : "+f"(d[0]), "+f"(d[1]), "+f"(d[2]), "+f"(d[3])
                 : "r"(a[0]), "r"(a[1]), "r"(a[2]), "r"(a[3]), "r"(b[0]), "r"(b[1]));
}
// vectorized f16x2 reduction (PTX ISA 8.1+, sm_90+, not arch-'a' gated)
__device__ __forceinline__ void red_add_v4_f16x2(__half* p, uint32_t a, uint32_t b,
                                                 uint32_t c2, uint32_t d2) {
    asm volatile("red.global.add.noftz.v4.f16x2 [%0], {%1, %2, %3, %4};"
                 :: "l"(p), "r"(a), "r"(b), "r"(c2), "r"(d2) : "memory");
}

// fast sigmoid/tanh via ex2/rcp approx (rel err ~1e-6)
__device__ __forceinline__ float fexp2_(float x) {
    float y; asm("ex2.approx.ftz.f32 %0, %1;" : "=f"(y) : "f"(x)); return y;
}
__device__ __forceinline__ float frcp_(float x) {
    float y; asm("rcp.approx.ftz.f32 %0, %1;" : "=f"(y) : "f"(x)); return y;
}
__device__ __forceinline__ float sig_(float x) {
    return frcp_(1.0f + fexp2_(-1.4426950408889634f * x));
}
__device__ __forceinline__ float tanh_(float x) {
    return 2.0f * frcp_(1.0f + fexp2_(-2.8853900817779268f * x)) - 1.0f;
}

// ---------------------------------------------------------------------------
// Kernel 0: zero fp16 accumulators (204.8 MB total)
// ---------------------------------------------------------------------------
__global__ void zero_kernel() {
    long long idx = (long long)blockIdx.x * blockDim.x + threadIdx.x;
    long long total4 = (long long)NNODES * HSZ / 8;   // uint4 = 8 halves
    uint4 z = make_uint4(0u, 0u, 0u, 0u);
    for (long long i = idx; i < total4; i += (long long)gridDim.x * blockDim.x) {
        ((uint4*)g_hsum)[i] = z;
        ((uint4*)g_csum)[i] = z;
    }
}

// ---------------------------------------------------------------------------
// Kernel 1: pack weights -> fp16, layout [n][k] K-major, n = 4q+t
// ---------------------------------------------------------------------------
__global__ void pack_kernel(const float* __restrict__ Wiou,
                            const float* __restrict__ Uiou,
                            const float* __restrict__ biou,
                            const float* __restrict__ Ufw,
                            const float* __restrict__ Ufb) {
    int idx = blockIdx.x * blockDim.x + threadIdx.x;
    if (idx < NOUT * KK) {
        int n = idx >> 9;
        int k = idx & (KK - 1);
        int q = n >> 2;
        int t = n & 3;
        float v;
        if (k < 256) {
            v = (t < 3) ? Wiou[(t * 256 + q) * XSZ + k] : 0.0f;
        } else {
            int kk = k - 256;
            v = (t < 3) ? Uiou[(t * 256 + q) * HSZ + kk] : Ufw[q * HSZ + kk];
        }
        g_Bf[idx] = __float2half_rn(v);
    }
    if (idx < NOUT) {
        int q = idx >> 2;
        int t = idx & 3;
        g_bias[idx] = (t < 3) ? biou[t * 256 + q] : Ufb[q];
    }
}

// ---------------------------------------------------------------------------
// Kernel 2: edge scatter-add, fp16x2 vector reductions (32 lanes/edge, 8 vals)
// ---------------------------------------------------------------------------
__global__ void scatter_kernel(const float* __restrict__ h,
                               const float* __restrict__ c,
                               const int* __restrict__ src,
                               const int* __restrict__ dst,
                               int E) {
    int e = blockIdx.x * 8 + (threadIdx.x >> 5);
    if (e >= E) return;
    int lane = threadIdx.x & 31;
    int s = src[e];
    int d = dst[e];
    int off = lane * 8;
    float4 h0 = __ldcs((const float4*)&h[(long long)s * HSZ + off]);
    float4 h1 = __ldcs((const float4*)&h[(long long)s * HSZ + off + 4]);
    float4 c0 = __ldcs((const float4*)&c[(long long)s * HSZ + off]);
    float4 c1 = __ldcs((const float4*)&c[(long long)s * HSZ + off + 4]);
    uint32_t ph0 = h2u(__floats2half2_rn(h0.x, h0.y));
    uint32_t ph1 = h2u(__floats2half2_rn(h0.z, h0.w));
    uint32_t ph2 = h2u(__floats2half2_rn(h1.x, h1.y));
    uint32_t ph3 = h2u(__floats2half2_rn(h1.z, h1.w));
    uint32_t pc0 = h2u(__floats2half2_rn(c0.x, c0.y));
    uint32_t pc1 = h2u(__floats2half2_rn(c0.z, c0.w));
    uint32_t pc2 = h2u(__floats2half2_rn(c1.x, c1.y));
    uint32_t pc3 = h2u(__floats2half2_rn(c1.z, c1.w));
    red_add_v4_f16x2(&g_hsum[(long long)d * HSZ + off], ph0, ph1, ph2, ph3);
    red_add_v4_f16x2(&g_csum[(long long)d * HSZ + off], pc0, pc1, pc2, pc3);
}

// ---------------------------------------------------------------------------
// Kernel 3: convert x -> fp16 [m][256] (h-half of A is g_hsum directly)
// ---------------------------------------------------------------------------
__global__ void convert_kernel(const float* __restrict__ x, int M) {
    long long i = (long long)blockIdx.x * blockDim.x + threadIdx.x;
    long long total = (long long)M * 64;           // one float4 each
    if (i >= total) return;
    int m = (int)(i >> 6);
    int k = ((int)i & 63) * 4;
    float4 v = *(const float4*)&x[(long long)m * XSZ + k];
    __half2 h01 = __floats2half2_rn(v.x, v.y);
    __half2 h23 = __floats2half2_rn(v.z, v.w);
    long long off = (long long)m * XSZ + k;
    *(__half2*)&g_Ax[off + 0] = h01;
    *(__half2*)&g_Ax[off + 2] = h23;
}

// ---------------------------------------------------------------------------
// Kernel 4: fp16 mma.sync GEMM (128x128xK512, BK=64) + coalesced fused epilogue
//   A's k<256 half from g_Ax, k>=256 half from g_hsum (both fp16 [m][256])
// ---------------------------------------------------------------------------
#define BK        64
#define ROWB      144                      // padded row bytes (72 halves)
#define SEC_B     (128 * ROWB)             // 18432 B per matrix section
#define STAGE_B   (2 * SEC_B)              // 36864 B
#define NSTG      3
#define KITERS    (KK / BK)                // 8
#define DYN_SMEM  (NSTG * STAGE_B)         // 110592 B
#define SST       136                      // epilogue smem row stride (words)

__global__ void __launch_bounds__(256, 2)
gemm_mma_kernel(float* __restrict__ hout, float* __restrict__ cout, int M) {
    extern __shared__ __align__(128) char sm[];
    __shared__ __align__(16) float s_bias[128];   // 16B-aligned: read as float4

    const int tid  = threadIdx.x;
    const int lane = tid & 31;
    const int wid  = tid >> 5;
    const int wm   = wid >> 2;            // 0..1  (64-row band)
    const int wn   = wid & 3;             // 0..3  (32-col band)
    const int m0   = blockIdx.y * 128;
    const int n0   = blockIdx.x * 128;
    const uint32_t smb = s2u(sm);

    if (tid < 128) s_bias[tid] = g_bias[n0 + tid];

    // ---- stage loader: 2048 x 16B cp.async ---------------------------------
    auto load_stage = [&](int s) {
        const uint32_t base = smb + (s % NSTG) * STAGE_B;
        const int k0 = s * BK;
        const __half* Asrc = (k0 < 256) ? g_Ax : (const __half*)g_hsum;
        const int ka = (k0 < 256) ? k0 : (k0 - 256);
#pragma unroll
        for (int i = 0; i < 8; i++) {
            int l = tid + i * 256;
            int sec = l >> 10;            // 0=A 1=B
            int w = l & 1023;
            int row = w >> 3;             // 0..127
            int ch = w & 7;               // 0..7 chunks of 8 halves
            const __half* src;
            if (sec == 0) {
                int gr = m0 + row; if (gr >= M) gr = M - 1;
                src = Asrc + (long long)gr * 256 + ka + ch * 8;
            } else {
                src = g_Bf + (long long)(n0 + row) * KK + k0 + ch * 8;
            }
            uint32_t dst = base + sec * SEC_B + row * ROWB + ch * 16;
            CPA16(dst, src);
        }
        CPA_COMMIT();
    };

    load_stage(0);
    load_stage(1);

    float acc[4][4][4];
#pragma unroll
    for (int i = 0; i < 4; i++)
#pragma unroll
        for (int j = 0; j < 4; j++)
#pragma unroll
            for (int p = 0; p < 4; p++) acc[i][j][p] = 0.0f;

    const uint32_t aRow = (wm * 64 + (lane & 15)) * ROWB + (lane >> 4) * 16;
    const uint32_t bRow = (wn * 32 + (lane & 7) + ((lane >> 4) & 1) * 8) * ROWB
                          + ((lane >> 3) & 1) * 16;

#pragma unroll 1
    for (int s = 0; s < KITERS; s++) {
        if (s < KITERS - 1) asm volatile("cp.async.wait_group 1;" ::: "memory");
        else                asm volatile("cp.async.wait_group 0;" ::: "memory");
        __syncthreads();
        // prefetch stage s+2 into buffer (s-1)%3 (consumed at iter s-1)
        if (s + 2 < KITERS) load_stage(s + 2);

        const uint32_t base = smb + (s % NSTG) * STAGE_B;
#pragma unroll
        for (int t = 0; t < 4; t++) {
            const uint32_t kb = t * 32;
            uint32_t ah[4][4], bh[2][4];
#pragma unroll
            for (int i = 0; i < 4; i++)
                ldsm4(ah[i], base + 0 * SEC_B + aRow + i * 16 * ROWB + kb);
#pragma unroll
            for (int j = 0; j < 2; j++)
                ldsm4(bh[j], base + 1 * SEC_B + bRow + j * 16 * ROWB + kb);
#pragma unroll
            for (int i = 0; i < 4; i++) {
#pragma unroll
                for (int jt = 0; jt < 4; jt++) {
                    mma16816(acc[i][jt], ah[i], &bh[jt >> 1][(jt & 1) * 2]);
                }
            }
        }
    }

    // ---- epilogue: prefetch csum (fp16), then smem transpose --------------
    const int row  = tid >> 1;
    const int half = tid & 1;
    const int mrow = m0 + row;
    const bool valid = (mrow < M);
    const int qg0 = (n0 >> 2) + half * 16;
    uint4 csA = make_uint4(0u, 0u, 0u, 0u), csB = make_uint4(0u, 0u, 0u, 0u);
    if (valid) {
        const __half* csrow = g_csum + (long long)mrow * HSZ + qg0;
        csA = __ldcs((const uint4*)csrow);          // q+0..7  (fp16)
        csB = __ldcs((const uint4*)(csrow + 8));    // q+8..15 (fp16)
    }

    __syncthreads();            // all MMAs done; stage buffers reusable
    float* S = (float*)sm;      // [128][SST]
    {
        const int r0 = wm * 64 + (lane >> 2);
        const int c0 = wn * 32 + (lane & 3) * 2;
#pragma unroll
        for (int i = 0; i < 4; i++) {
#pragma unroll
            for (int jt = 0; jt < 4; jt++) {
                const int r = r0 + i * 16;
                const int c = c0 + jt * 8;
                *(float2*)&S[r * SST + c]       = make_float2(acc[i][jt][0], acc[i][jt][1]);
                *(float2*)&S[(r + 8) * SST + c] = make_float2(acc[i][jt][2], acc[i][jt][3]);
            }
        }
    }
    __syncthreads();

    // ---- coalesced TreeLSTM ------------------------------------------------
    if (valid) {
        const long long mb = (long long)mrow * HSZ;
        const float* Srow = &S[row * SST + half * 64];
        const float4* bq = &((const float4*)s_bias)[half * 16];
        float csf[16];
        {
            __half2 pa[4], pb[4];
            memcpy(pa, &csA, 16);
            memcpy(pb, &csB, 16);
#pragma unroll
            for (int i = 0; i < 4; i++) {
                float2 fa = __half22float2(pa[i]);
                float2 fb = __half22float2(pb[i]);
                csf[2 * i + 0] = fa.x; csf[2 * i + 1] = fa.y;
                csf[8 + 2 * i + 0] = fb.x; csf[8 + 2 * i + 1] = fb.y;
            }
        }
#pragma unroll
        for (int v = 0; v < 4; v++) {
            float hv[4], cv[4];
#pragma unroll
            for (int u = 0; u < 4; u++) {
                const int qq = v * 4 + u;
                float4 z = *(const float4*)&Srow[qq * 4];
                float4 b = bq[qq];
                float zi = z.x + b.x, zo = z.y + b.y;
                float zu = z.z + b.z, zf = z.w + b.w;
                float cs = csf[qq];
                float cn = sig_(zi) * tanh_(zu) + sig_(zf) * cs;
                cv[u] = cn;
                hv[u] = sig_(zo) * tanh_(cn);
            }
            __stcs((float4*)&hout[mb + qg0 + v * 4],
                   make_float4(hv[0], hv[1], hv[2], hv[3]));
            __stcs((float4*)&cout[mb + qg0 + v * 4],
                   make_float4(cv[0], cv[1], cv[2], cv[3]));
        }
    }
}

// ---------------------------------------------------------------------------
// launch
// ---------------------------------------------------------------------------
extern "C" void kernel_launch(void* const* d_in, const int* in_sizes, int n_in,
                              void* d_out, int out_size) {
    const float* x    = (const float*)d_in[0];
    const float* h    = (const float*)d_in[1];
    const float* c    = (const float*)d_in[2];
    const int*   src  = (const int*)d_in[3];
    const int*   dst  = (const int*)d_in[4];
    const float* Wiou = (const float*)d_in[5];
    const float* Uiou = (const float*)d_in[6];
    const float* biou = (const float*)d_in[7];
    const float* Ufw  = (const float*)d_in[8];
    const float* Ufb  = (const float*)d_in[9];

    const int E = in_sizes[3];
    const int M = in_sizes[0] / XSZ;

    float* hout = (float*)d_out;
    float* cout = (float*)d_out + (long long)M * HSZ;

    cudaFuncSetAttribute(gemm_mma_kernel,
                         cudaFuncAttributeMaxDynamicSharedMemorySize, DYN_SMEM);

    zero_kernel<<<4096, 256>>>();
    pack_kernel<<<(NOUT * KK + 255) / 256, 256>>>(Wiou, Uiou, biou, Ufw, Ufb);
    scatter_kernel<<<(E + 7) / 8, 256>>>(h, c, src, dst, E);
    convert_kernel<<<(int)(((long long)M * 64 + 255) / 256), 256>>>(x, M);

    dim3 grid(NOUT / 128, (M + 127) / 128);
    gemm_mma_kernel<<<grid, 256, DYN_SMEM>>>(hout, cout, M);
}

// round 14
// speedup vs baseline: 1.4710x; 1.0035x over previous
#include <cuda_runtime.h>
#include <cuda_fp16.h>
#include <math.h>
#include <stdint.h>
#include <string.h>

// Problem constants (fixed by the dataset)
#define NNODES 200000
#define HSZ    256
#define XSZ    256
#define KK     512          // packed K = XSZ + HSZ
#define NOUT   1024         // packed cols, interleaved gate quads (i,o,u,f)

// ---------------- device scratch (static allocation) ------------------------
__device__ __half g_hsum[(size_t)NNODES * HSZ];        // 102.4 MB fp16 accumulator (= A's h-half)
__device__ __half g_csum[(size_t)NNODES * HSZ];        // 102.4 MB fp16 accumulator
__device__ __half g_Ax[(size_t)NNODES * XSZ];          // 102.4 MB x -> fp16
__device__ __half g_Bf[NOUT * KK];                     // 1 MB  [n][k] K-major
__device__ float g_bias[NOUT];

// ---------------- PTX helpers (baseline compute_103 only) -------------------
__device__ __forceinline__ uint32_t s2u(const void* p) {
    uint32_t a;
    asm("{ .reg .u64 t; cvta.to.shared.u64 t, %1; cvt.u32.u64 %0, t; }"
        : "=r"(a) : "l"(p));
    return a;
}
__device__ __forceinline__ uint32_t h2u(__half2 v) {
    uint32_t u;
    memcpy(&u, &v, 4);
    return u;
}
#define CPA16(dst, src) \
    asm volatile("cp.async.cg.shared.global [%0], [%1], 16;" :: "r"(dst), "l"(src) : "memory")
#define CPA_COMMIT() asm volatile("cp.async.commit_group;" ::: "memory")

__device__ __forceinline__ void ldsm4(uint32_t* r, uint32_t addr) {
    asm volatile("ldmatrix.sync.aligned.m8n8.x4.shared.b16 {%0,%1,%2,%3}, [%4];"
                 : "=r"(r[0]), "=r"(r[1]), "=r"(r[2]), "=r"(r[3]) : "r"(addr));
}
__device__ __forceinline__ void mma16816(float* d, const uint32_t* a, const uint32_t* b) {
    asm volatile("mma.sync.aligned.m16n8k16.row.col.f32.f16.f16.f32 "
                 "{%0,%1,%2,%3}, {%4,%5,%6,%7}, {%8,%9}, {%0,%1,%2,%3};"
                 : "+f"(d[0]), "+f"(d[1]), "+f"(d[2]), "+f"(d[3])
                 : "r"(a[0]), "r"(a[1]), "r"(a[2]), "r"(a[3]), "r"(b[0]), "r"(b[1]));
}
// vectorized f16x2 reduction (PTX ISA 8.1+, sm_90+, not arch-'a' gated)
__device__ __forceinline__ void red_add_v4_f16x2(__half* p, uint32_t a, uint32_t b,
                                                 uint32_t c2, uint32_t d2) {
    asm volatile("red.global.add.noftz.v4.f16x2 [%0], {%1, %2, %3, %4};"
                 :: "l"(p), "r"(a), "r"(b), "r"(c2), "r"(d2) : "memory");
}

// fast sigmoid/tanh via ex2/rcp approx (rel err ~1e-6)
__device__ __forceinline__ float fexp2_(float x) {
    float y; asm("ex2.approx.ftz.f32 %0, %1;" : "=f"(y) : "f"(x)); return y;
}
__device__ __forceinline__ float frcp_(float x) {
    float y; asm("rcp.approx.ftz.f32 %0, %1;" : "=f"(y) : "f"(x)); return y;
}
__device__ __forceinline__ float sig_(float x) {
    return frcp_(1.0f + fexp2_(-1.4426950408889634f * x));
}
__device__ __forceinline__ float tanh_(float x) {
    return 2.0f * frcp_(1.0f + fexp2_(-2.8853900817779268f * x)) - 1.0f;
}

// ---------------------------------------------------------------------------
// Kernel 0: zero fp16 accumulators + pack weights (merged, block-range split)
// ---------------------------------------------------------------------------
#define ZERO_BLKS 4096
#define PACK_BLKS ((NOUT * KK + 255) / 256)

__global__ void zero_pack_kernel(const float* __restrict__ Wiou,
                                 const float* __restrict__ Uiou,
                                 const float* __restrict__ biou,
                                 const float* __restrict__ Ufw,
                                 const float* __restrict__ Ufb) {
    if (blockIdx.x < ZERO_BLKS) {
        long long idx = (long long)blockIdx.x * blockDim.x + threadIdx.x;
        long long total4 = (long long)NNODES * HSZ / 8;   // uint4 = 8 halves
        uint4 z = make_uint4(0u, 0u, 0u, 0u);
        for (long long i = idx; i < total4; i += (long long)ZERO_BLKS * 256) {
            ((uint4*)g_hsum)[i] = z;
            ((uint4*)g_csum)[i] = z;
        }
    } else {
        int idx = (blockIdx.x - ZERO_BLKS) * 256 + threadIdx.x;
        if (idx < NOUT * KK) {
            int n = idx >> 9;
            int k = idx & (KK - 1);
            int q = n >> 2;
            int t = n & 3;
            float v;
            if (k < 256) {
                v = (t < 3) ? Wiou[(t * 256 + q) * XSZ + k] : 0.0f;
            } else {
                int kk = k - 256;
                v = (t < 3) ? Uiou[(t * 256 + q) * HSZ + kk] : Ufw[q * HSZ + kk];
            }
            g_Bf[idx] = __float2half_rn(v);
        }
        if (idx < NOUT) {
            int q = idx >> 2;
            int t = idx & 3;
            g_bias[idx] = (t < 3) ? biou[t * 256 + q] : Ufb[q];
        }
    }
}

// ---------------------------------------------------------------------------
// Kernel 1: convert x -> fp16 (streaming) + edge scatter-add (RMW), merged so
//   the streaming part hides the atomic latency of the scatter part.
// ---------------------------------------------------------------------------
__global__ void scatter_convert_kernel(const float* __restrict__ h,
                                       const float* __restrict__ c,
                                       const int* __restrict__ src,
                                       const int* __restrict__ dst,
                                       const float* __restrict__ x,
                                       int E, int M, int convBlocks) {
    if (blockIdx.x < convBlocks) {
        long long i = (long long)blockIdx.x * 256 + threadIdx.x;
        long long total = (long long)M * 64;           // one float4 each
        if (i >= total) return;
        int m = (int)(i >> 6);
        int k = ((int)i & 63) * 4;
        float4 v = *(const float4*)&x[(long long)m * XSZ + k];
        __half2 h01 = __floats2half2_rn(v.x, v.y);
        __half2 h23 = __floats2half2_rn(v.z, v.w);
        long long off = (long long)m * XSZ + k;
        *(__half2*)&g_Ax[off + 0] = h01;
        *(__half2*)&g_Ax[off + 2] = h23;
    } else {
        int e = (blockIdx.x - convBlocks) * 8 + (threadIdx.x >> 5);
        if (e >= E) return;
        int lane = threadIdx.x & 31;
        int s = src[e];
        int d = dst[e];
        int off = lane * 8;
        float4 h0 = __ldcs((const float4*)&h[(long long)s * HSZ + off]);
        float4 h1 = __ldcs((const float4*)&h[(long long)s * HSZ + off + 4]);
        float4 c0 = __ldcs((const float4*)&c[(long long)s * HSZ + off]);
        float4 c1 = __ldcs((const float4*)&c[(long long)s * HSZ + off + 4]);
        uint32_t ph0 = h2u(__floats2half2_rn(h0.x, h0.y));
        uint32_t ph1 = h2u(__floats2half2_rn(h0.z, h0.w));
        uint32_t ph2 = h2u(__floats2half2_rn(h1.x, h1.y));
        uint32_t ph3 = h2u(__floats2half2_rn(h1.z, h1.w));
        uint32_t pc0 = h2u(__floats2half2_rn(c0.x, c0.y));
        uint32_t pc1 = h2u(__floats2half2_rn(c0.z, c0.w));
        uint32_t pc2 = h2u(__floats2half2_rn(c1.x, c1.y));
        uint32_t pc3 = h2u(__floats2half2_rn(c1.z, c1.w));
        red_add_v4_f16x2(&g_hsum[(long long)d * HSZ + off], ph0, ph1, ph2, ph3);
        red_add_v4_f16x2(&g_csum[(long long)d * HSZ + off], pc0, pc1, pc2, pc3);
    }
}

// ---------------------------------------------------------------------------
// Kernel 2: fp16 mma.sync GEMM (128x128xK512, BK=64) + coalesced fused epilogue
//   3-stage cp.async pipeline, fragment double-buffering in the t-loop
// ---------------------------------------------------------------------------
#define BK        64
#define ROWB      144                      // padded row bytes (72 halves)
#define SEC_B     (128 * ROWB)             // 18432 B per matrix section
#define STAGE_B   (2 * SEC_B)              // 36864 B
#define NSTG      3
#define KITERS    (KK / BK)                // 8
#define DYN_SMEM  (NSTG * STAGE_B)         // 110592 B
#define SST       136                      // epilogue smem row stride (words)

__global__ void __launch_bounds__(256, 2)
gemm_mma_kernel(float* __restrict__ hout, float* __restrict__ cout, int M) {
    extern __shared__ __align__(128) char sm[];
    __shared__ __align__(16) float s_bias[128];   // 16B-aligned: read as float4

    const int tid  = threadIdx.x;
    const int lane = tid & 31;
    const int wid  = tid >> 5;
    const int wm   = wid >> 2;            // 0..1  (64-row band)
    const int wn   = wid & 3;             // 0..3  (32-col band)
    const int m0   = blockIdx.y * 128;
    const int n0   = blockIdx.x * 128;
    const uint32_t smb = s2u(sm);

    if (tid < 128) s_bias[tid] = g_bias[n0 + tid];

    // ---- stage loader: 2048 x 16B cp.async ---------------------------------
    auto load_stage = [&](int s) {
        const uint32_t base = smb + (s % NSTG) * STAGE_B;
        const int k0 = s * BK;
        const __half* Asrc = (k0 < 256) ? g_Ax : (const __half*)g_hsum;
        const int ka = (k0 < 256) ? k0 : (k0 - 256);
#pragma unroll
        for (int i = 0; i < 8; i++) {
            int l = tid + i * 256;
            int sec = l >> 10;            // 0=A 1=B
            int w = l & 1023;
            int row = w >> 3;             // 0..127
            int ch = w & 7;               // 0..7 chunks of 8 halves
            const __half* src;
            if (sec == 0) {
                int gr = m0 + row; if (gr >= M) gr = M - 1;
                src = Asrc + (long long)gr * 256 + ka + ch * 8;
            } else {
                src = g_Bf + (long long)(n0 + row) * KK + k0 + ch * 8;
            }
            uint32_t dst = base + sec * SEC_B + row * ROWB + ch * 16;
            CPA16(dst, src);
        }
        CPA_COMMIT();
    };

    load_stage(0);
    load_stage(1);

    float acc[4][4][4];
#pragma unroll
    for (int i = 0; i < 4; i++)
#pragma unroll
        for (int j = 0; j < 4; j++)
#pragma unroll
            for (int p = 0; p < 4; p++) acc[i][j][p] = 0.0f;

    const uint32_t aRow = (wm * 64 + (lane & 15)) * ROWB + (lane >> 4) * 16;
    const uint32_t bRow = (wn * 32 + (lane & 7) + ((lane >> 4) & 1) * 8) * ROWB
                          + ((lane >> 3) & 1) * 16;

#pragma unroll 1
    for (int s = 0; s < KITERS; s++) {
        if (s < KITERS - 1) asm volatile("cp.async.wait_group 1;" ::: "memory");
        else                asm volatile("cp.async.wait_group 0;" ::: "memory");
        __syncthreads();

        const uint32_t base = smb + (s % NSTG) * STAGE_B;

        // fragment double buffer: load t=0 first, then cp.async burst
        uint32_t ah[2][4][4], bh[2][2][4];
#pragma unroll
        for (int i = 0; i < 4; i++)
            ldsm4(ah[0][i], base + 0 * SEC_B + aRow + i * 16 * ROWB);
#pragma unroll
        for (int j = 0; j < 2; j++)
            ldsm4(bh[0][j], base + 1 * SEC_B + bRow + j * 16 * ROWB);

        // prefetch stage s+2 into buffer (s-1)%3 (consumed at iter s-1)
        if (s + 2 < KITERS) load_stage(s + 2);

#pragma unroll
        for (int t = 0; t < 4; t++) {
            const int cur = t & 1;
            if (t < 3) {
                const int nxt = cur ^ 1;
                const uint32_t kb = (t + 1) * 32;
#pragma unroll
                for (int i = 0; i < 4; i++)
                    ldsm4(ah[nxt][i], base + 0 * SEC_B + aRow + i * 16 * ROWB + kb);
#pragma unroll
                for (int j = 0; j < 2; j++)
                    ldsm4(bh[nxt][j], base + 1 * SEC_B + bRow + j * 16 * ROWB + kb);
            }
#pragma unroll
            for (int i = 0; i < 4; i++) {
#pragma unroll
                for (int jt = 0; jt < 4; jt++) {
                    mma16816(acc[i][jt], ah[cur][i], &bh[cur][jt >> 1][(jt & 1) * 2]);
                }
            }
        }
    }

    // ---- epilogue: prefetch csum (fp16), then smem transpose --------------
    const int row  = tid >> 1;
    const int half = tid & 1;
    const int mrow = m0 + row;
    const bool valid = (mrow < M);
    const int qg0 = (n0 >> 2) + half * 16;
    uint4 csA = make_uint4(0u, 0u, 0u, 0u), csB = make_uint4(0u, 0u, 0u, 0u);
    if (valid) {
        const __half* csrow = g_csum + (long long)mrow * HSZ + qg0;
        csA = __ldcs((const uint4*)csrow);          // q+0..7  (fp16)
        csB = __ldcs((const uint4*)(csrow + 8));    // q+8..15 (fp16)
    }

    __syncthreads();            // all MMAs done; stage buffers reusable
    float* S = (float*)sm;      // [128][SST]
    {
        const int r0 = wm * 64 + (lane >> 2);
        const int c0 = wn * 32 + (lane & 3) * 2;
#pragma unroll
        for (int i = 0; i < 4; i++) {
#pragma unroll
            for (int jt = 0; jt < 4; jt++) {
                const int r = r0 + i * 16;
                const int c = c0 + jt * 8;
                *(float2*)&S[r * SST + c]       = make_float2(acc[i][jt][0], acc[i][jt][1]);
                *(float2*)&S[(r + 8) * SST + c] = make_float2(acc[i][jt][2], acc[i][jt][3]);
            }
        }
    }
    __syncthreads();

    // ---- coalesced TreeLSTM ------------------------------------------------
    if (valid) {
        const long long mb = (long long)mrow * HSZ;
        const float* Srow = &S[row * SST + half * 64];
        const float4* bq = &((const float4*)s_bias)[half * 16];
        float csf[16];
        {
            __half2 pa[4], pb[4];
            memcpy(pa, &csA, 16);
            memcpy(pb, &csB, 16);
#pragma unroll
            for (int i = 0; i < 4; i++) {
                float2 fa = __half22float2(pa[i]);
                float2 fb = __half22float2(pb[i]);
                csf[2 * i + 0] = fa.x; csf[2 * i + 1] = fa.y;
                csf[8 + 2 * i + 0] = fb.x; csf[8 + 2 * i + 1] = fb.y;
            }
        }
#pragma unroll
        for (int v = 0; v < 4; v++) {
            float hv[4], cv[4];
#pragma unroll
            for (int u = 0; u < 4; u++) {
                const int qq = v * 4 + u;
                float4 z = *(const float4*)&Srow[qq * 4];
                float4 b = bq[qq];
                float zi = z.x + b.x, zo = z.y + b.y;
                float zu = z.z + b.z, zf = z.w + b.w;
                float cs = csf[qq];
                float cn = sig_(zi) * tanh_(zu) + sig_(zf) * cs;
                cv[u] = cn;
                hv[u] = sig_(zo) * tanh_(cn);
            }
            __stcs((float4*)&hout[mb + qg0 + v * 4],
                   make_float4(hv[0], hv[1], hv[2], hv[3]));
            __stcs((float4*)&cout[mb + qg0 + v * 4],
                   make_float4(cv[0], cv[1], cv[2], cv[3]));
        }
    }
}

// ---------------------------------------------------------------------------
// launch
// ---------------------------------------------------------------------------
extern "C" void kernel_launch(void* const* d_in, const int* in_sizes, int n_in,
                              void* d_out, int out_size) {
    const float* x    = (const float*)d_in[0];
    const float* h    = (const float*)d_in[1];
    const float* c    = (const float*)d_in[2];
    const int*   src  = (const int*)d_in[3];
    const int*   dst  = (const int*)d_in[4];
    const float* Wiou = (const float*)d_in[5];
    const float* Uiou = (const float*)d_in[6];
    const float* biou = (const float*)d_in[7];
    const float* Ufw  = (const float*)d_in[8];
    const float* Ufb  = (const float*)d_in[9];

    const int E = in_sizes[3];
    const int M = in_sizes[0] / XSZ;

    float* hout = (float*)d_out;
    float* cout = (float*)d_out + (long long)M * HSZ;

    cudaFuncSetAttribute(gemm_mma_kernel,
                         cudaFuncAttributeMaxDynamicSharedMemorySize, DYN_SMEM);

    zero_pack_kernel<<<ZERO_BLKS + PACK_BLKS, 256>>>(Wiou, Uiou, biou, Ufw, Ufb);

    const int convBlocks = (int)(((long long)M * 64 + 255) / 256);
    const int scatBlocks = (E + 7) / 8;
    scatter_convert_kernel<<<convBlocks + scatBlocks, 256>>>(h, c, src, dst, x,
                                                             E, M, convBlocks);

    dim3 grid(NOUT / 128, (M + 127) / 128);
    gemm_mma_kernel<<<grid, 256, DYN_SMEM>>>(hout, cout, M);
}